// round 1
// baseline (speedup 1.0000x reference)
#include <cuda_runtime.h>

#define TT 1024
#define NBLK 256
#define NTHR 256

struct Q { float w, x, y, z; };
struct V3 { float x, y, z; };

__device__ __forceinline__ Q qmul(const Q a, const Q b) {
    return Q{ a.w*b.w - a.x*b.x - a.y*b.y - a.z*b.z,
              a.w*b.x + a.x*b.w + a.y*b.z - a.z*b.y,
              a.w*b.y - a.x*b.z + a.y*b.w + a.z*b.x,
              a.w*b.z + a.x*b.y - a.y*b.x + a.z*b.w };
}
__device__ __forceinline__ Q qconj(const Q q) { return Q{q.w, -q.x, -q.y, -q.z}; }

__device__ __forceinline__ V3 qrot(const Q q, const V3 v) {
    // t = 2*cross(qv, v); out = v + w*t + cross(qv, t)
    float tx = 2.0f*(q.y*v.z - q.z*v.y);
    float ty = 2.0f*(q.z*v.x - q.x*v.z);
    float tz = 2.0f*(q.x*v.y - q.y*v.x);
    return V3{ v.x + q.w*tx + (q.y*tz - q.z*ty),
               v.y + q.w*ty + (q.z*tx - q.x*tz),
               v.z + q.w*tz + (q.x*ty - q.y*tx) };
}

__device__ __forceinline__ void qmat(const Q q, float m[9]) {
    m[0] = 1.0f - 2.0f*(q.y*q.y + q.z*q.z);
    m[1] = 2.0f*(q.x*q.y - q.w*q.z);
    m[2] = 2.0f*(q.x*q.z + q.w*q.y);
    m[3] = 2.0f*(q.x*q.y + q.w*q.z);
    m[4] = 1.0f - 2.0f*(q.x*q.x + q.z*q.z);
    m[5] = 2.0f*(q.y*q.z - q.w*q.x);
    m[6] = 2.0f*(q.x*q.z - q.w*q.y);
    m[7] = 2.0f*(q.y*q.z + q.w*q.x);
    m[8] = 1.0f - 2.0f*(q.x*q.x + q.y*q.y);
}

__device__ __forceinline__ float rmd2(const Q a, const Q b) {
    float ma[9], mb[9];
    qmat(a, ma); qmat(b, mb);
    float s = 0.0f;
#pragma unroll
    for (int i = 0; i < 9; i++) { float d = ma[i] - mb[i]; s = fmaf(d, d, s); }
    return s;
}

__device__ __forceinline__ V3 v3add(const V3 a, const V3 b) { return V3{a.x+b.x, a.y+b.y, a.z+b.z}; }
__device__ __forceinline__ float pd2(const V3 a, const V3 b) {
    float dx = a.x-b.x, dy = a.y-b.y, dz = a.z-b.z;
    return fmaf(dx, dx, fmaf(dy, dy, dz*dz));
}

// load 4 channels (stride TT), denorm with mean/std (indexed at mc..mc+3), normalize
__device__ __forceinline__ Q loadnq(const float* __restrict__ p, int src_c,
                                    const float* __restrict__ mn, const float* __restrict__ sd, int mc) {
    float w = fmaf(p[(src_c+0)*TT], sd[mc+0], mn[mc+0]);
    float x = fmaf(p[(src_c+1)*TT], sd[mc+1], mn[mc+1]);
    float y = fmaf(p[(src_c+2)*TT], sd[mc+2], mn[mc+2]);
    float z = fmaf(p[(src_c+3)*TT], sd[mc+3], mn[mc+3]);
    float inv = rsqrtf(fmaf(w, w, fmaf(x, x, fmaf(y, y, z*z))));
    return Q{w*inv, x*inv, y*inv, z*inv};
}

__device__ float g_part[NBLK];

__global__ void __launch_bounds__(NTHR) fk_loss_kernel(
    const float* __restrict__ ik,   // (64, 168, 1024)
    const float* __restrict__ dec,  // (64, 176, 1024)
    const float* __restrict__ tgt,  // (64, 176, 1024)
    const float* __restrict__ mean, // (176,)
    const float* __restrict__ stdv, // (176,)
    const float* __restrict__ offs) // (22, 3)
{
    __shared__ float smn[176], ssd[176], soff[66];
    for (int i = threadIdx.x; i < 176; i += NTHR) { smn[i] = mean[i]; ssd[i] = stdv[i]; }
    for (int i = threadIdx.x; i < 66; i += NTHR) soff[i] = offs[i];
    __syncthreads();

    int tid = blockIdx.x * NTHR + threadIdx.x;
    int b = tid >> 10, t = tid & 1023;
    const float* ikp = ik  + (size_t)b * 168 * TT + t;
    const float* dcp = dec + (size_t)b * 176 * TT + t;
    const float* tgp = tgt + (size_t)b * 176 * TT + t;

    // target root quat (ik/dec roots are forced to identity)
    Q qc0 = qconj(loadnq(tgp, 0, smn, ssd, 0));

    // per-chain global rot + position state; static indices only -> registers
    Q  gI[22], gD[22], gT[22];
    V3 pI[22], pD[22], pT[22];

    float aep = 0.0f, aer = 0.0f, anp = 0.0f, anr = 0.0f;

    // NS joint: all three chains advance; loss term dec-vs-ik (pos + rotmat)
#define STEP_NS(j, p) do {                                                     \
    Q qi = loadnq(ikp, ((j)-1)*8, smn, ssd, (j)*8);                            \
    Q qd = loadnq(dcp, (j)*8,     smn, ssd, (j)*8);                            \
    Q qt = loadnq(tgp, (j)*8,     smn, ssd, (j)*8);                            \
    gI[j] = qi; gD[j] = qd; gT[j] = qmul(qc0, qt);                             \
    V3 off = V3{soff[3*(j)], soff[3*(j)+1], soff[3*(j)+2]};                    \
    if ((p) == 0) { pI[j] = off; pD[j] = off; pT[j] = off; }                   \
    else {                                                                     \
        pI[j] = v3add(qrot(gI[p], off), pI[p]);                                \
        pD[j] = v3add(qrot(gD[p], off), pD[p]);                                \
        pT[j] = v3add(qrot(gT[p], off), pT[p]);                                \
    }                                                                          \
    anp += pd2(pD[j], pI[j]);                                                  \
    anr += rmd2(gD[j], gI[j]);                                                 \
} while (0)

    // EE joint (always a leaf, parent != 0): dec chain skipped; loss ik-vs-tgt
#define STEP_EE(j, p) do {                                                     \
    Q qi = loadnq(ikp, ((j)-1)*8, smn, ssd, (j)*8);                            \
    Q qt = loadnq(tgp, (j)*8,     smn, ssd, (j)*8);                            \
    Q gi = qi; Q gt = qmul(qc0, qt);                                           \
    V3 off = V3{soff[3*(j)], soff[3*(j)+1], soff[3*(j)+2]};                    \
    V3 Pi = v3add(qrot(gI[p], off), pI[p]);                                    \
    V3 Pt = v3add(qrot(gT[p], off), pT[p]);                                    \
    aep += pd2(Pi, Pt);                                                        \
    aer += rmd2(gi, gt);                                                       \
} while (0)

    STEP_NS(1, 0);  STEP_NS(2, 1);  STEP_NS(3, 2);   STEP_EE(4, 3);
    STEP_NS(5, 0);  STEP_NS(6, 5);  STEP_NS(7, 6);   STEP_EE(8, 7);
    STEP_NS(9, 0);  STEP_NS(10, 9); STEP_NS(11, 10);
    STEP_NS(12, 11); STEP_EE(13, 12);
    STEP_NS(14, 11); STEP_NS(15, 14); STEP_NS(16, 15); STEP_EE(17, 16);
    STEP_NS(18, 11); STEP_NS(19, 18); STEP_NS(20, 19); STEP_EE(21, 20);

#undef STEP_NS
#undef STEP_EE

    // per-thread weighted contribution (mse denominators folded in)
    const float NBT = 65536.0f;
    float s = aep * (1.0f / (NBT * 15.0f))
            + aer * (1.0f / (NBT * 45.0f))
            + anp * (0.1f / (NBT * 48.0f))
            + anr * (0.1f / (NBT * 144.0f));

    // block reduction -> deterministic per-block partial
#pragma unroll
    for (int o = 16; o; o >>= 1) s += __shfl_down_sync(0xffffffffu, s, o);
    __shared__ float ws[NTHR / 32];
    if ((threadIdx.x & 31) == 0) ws[threadIdx.x >> 5] = s;
    __syncthreads();
    if (threadIdx.x == 0) {
        float v = 0.0f;
#pragma unroll
        for (int i = 0; i < NTHR / 32; i++) v += ws[i];
        g_part[blockIdx.x] = v;
    }
}

__global__ void __launch_bounds__(NBLK) final_reduce_kernel(float* __restrict__ out) {
    float v = g_part[threadIdx.x];
#pragma unroll
    for (int o = 16; o; o >>= 1) v += __shfl_down_sync(0xffffffffu, v, o);
    __shared__ float ws[NBLK / 32];
    if ((threadIdx.x & 31) == 0) ws[threadIdx.x >> 5] = v;
    __syncthreads();
    if (threadIdx.x == 0) {
        float s = 0.0f;
#pragma unroll
        for (int i = 0; i < NBLK / 32; i++) s += ws[i];
        out[0] = s;
    }
}

extern "C" void kernel_launch(void* const* d_in, const int* in_sizes, int n_in,
                              void* d_out, int out_size) {
    // metadata order: input(unused), input_ik, input_decoder, target, mean_dqs, std_dqs, offsets
    const float* ik   = (const float*)d_in[1];
    const float* dec  = (const float*)d_in[2];
    const float* tgt  = (const float*)d_in[3];
    const float* mean = (const float*)d_in[4];
    const float* stdv = (const float*)d_in[5];
    const float* offs = (const float*)d_in[6];
    float* out = (float*)d_out;

    fk_loss_kernel<<<NBLK, NTHR>>>(ik, dec, tgt, mean, stdv, offs);
    final_reduce_kernel<<<1, NBLK>>>(out);
}

// round 2
// speedup vs baseline: 1.2959x; 1.2959x over previous
#include <cuda_runtime.h>

#define TT 1024
#define NBLK 256
#define NTHR 256

struct Q { float w, x, y, z; };
struct V3 { float x, y, z; };

__device__ __forceinline__ Q qmul(const Q a, const Q b) {
    return Q{ a.w*b.w - a.x*b.x - a.y*b.y - a.z*b.z,
              a.w*b.x + a.x*b.w + a.y*b.z - a.z*b.y,
              a.w*b.y - a.x*b.z + a.y*b.w + a.z*b.x,
              a.w*b.z + a.x*b.y - a.y*b.x + a.z*b.w };
}
__device__ __forceinline__ Q qconj(const Q q) { return Q{q.w, -q.x, -q.y, -q.z}; }

__device__ __forceinline__ V3 qrot(const Q q, const V3 v) {
    float tx = 2.0f*(q.y*v.z - q.z*v.y);
    float ty = 2.0f*(q.z*v.x - q.x*v.z);
    float tz = 2.0f*(q.x*v.y - q.y*v.x);
    return V3{ v.x + q.w*tx + (q.y*tz - q.z*ty),
               v.y + q.w*ty + (q.z*tx - q.x*tz),
               v.z + q.w*tz + (q.x*ty - q.y*tx) };
}

// ||R(a)-R(b)||_F^2 = 8*(1 - dot(a,b)^2) for unit quats; we accumulate (1-dot^2)
__device__ __forceinline__ float qdot(const Q a, const Q b) {
    return fmaf(a.w, b.w, fmaf(a.x, b.x, fmaf(a.y, b.y, a.z*b.z)));
}

__device__ __forceinline__ V3 v3add(const V3 a, const V3 b) { return V3{a.x+b.x, a.y+b.y, a.z+b.z}; }
__device__ __forceinline__ float pd2(const V3 a, const V3 b) {
    float dx = a.x-b.x, dy = a.y-b.y, dz = a.z-b.z;
    return fmaf(dx, dx, fmaf(dy, dy, dz*dz));
}

__device__ __forceinline__ Q loadnq(const float* __restrict__ p, int src_c,
                                    const float* __restrict__ mn, const float* __restrict__ sd, int mc) {
    float w = fmaf(p[(src_c+0)*TT], sd[mc+0], mn[mc+0]);
    float x = fmaf(p[(src_c+1)*TT], sd[mc+1], mn[mc+1]);
    float y = fmaf(p[(src_c+2)*TT], sd[mc+2], mn[mc+2]);
    float z = fmaf(p[(src_c+3)*TT], sd[mc+3], mn[mc+3]);
    float inv = rsqrtf(fmaf(w, w, fmaf(x, x, fmaf(y, y, z*z))));
    return Q{w*inv, x*inv, y*inv, z*inv};
}

__device__ float g_part[NBLK];
__device__ unsigned int g_ctr = 0;

__global__ void __launch_bounds__(NTHR) fk_loss_kernel(
    const float* __restrict__ ik,   // (64, 168, 1024)
    const float* __restrict__ dec,  // (64, 176, 1024)
    const float* __restrict__ tgt,  // (64, 176, 1024)
    const float* __restrict__ mean, // (176,)
    const float* __restrict__ stdv, // (176,)
    const float* __restrict__ offs, // (22, 3)
    float* __restrict__ out)
{
    __shared__ float smn[176], ssd[176], soff[66];
    for (int i = threadIdx.x; i < 176; i += NTHR) { smn[i] = mean[i]; ssd[i] = stdv[i]; }
    for (int i = threadIdx.x; i < 66; i += NTHR) soff[i] = offs[i];
    __syncthreads();

    int tid = blockIdx.x * NTHR + threadIdx.x;
    int b = tid >> 10, t = tid & 1023;
    const float* ikp = ik  + (size_t)b * 168 * TT + t;
    const float* dcp = dec + (size_t)b * 176 * TT + t;
    const float* tgp = tgt + (size_t)b * 176 * TT + t;

    // target root quat (ik/dec roots are identity)
    Q qc0 = qconj(loadnq(tgp, 0, smn, ssd, 0));

    Q  gI[22], gD[22], gT[22];
    V3 pI[22], pD[22], pT[22];

    float aep = 0.0f, aer = 0.0f, anp = 0.0f, anr = 0.0f;

    // NS joint: all three chains advance; loss term dec-vs-ik (pos + rot)
    // rot term uses raw local quats: gD=qd, gI=qi since roots are identity.
#define STEP_NS(j, p) do {                                                     \
    Q qi = loadnq(ikp, ((j)-1)*8, smn, ssd, (j)*8);                            \
    Q qd = loadnq(dcp, (j)*8,     smn, ssd, (j)*8);                            \
    Q qt = loadnq(tgp, (j)*8,     smn, ssd, (j)*8);                            \
    gI[j] = qi; gD[j] = qd; gT[j] = qmul(qc0, qt);                             \
    V3 off = V3{soff[3*(j)], soff[3*(j)+1], soff[3*(j)+2]};                    \
    if ((p) == 0) { pI[j] = off; pD[j] = off; pT[j] = off; }                   \
    else {                                                                     \
        pI[j] = v3add(qrot(gI[p], off), pI[p]);                                \
        pD[j] = v3add(qrot(gD[p], off), pD[p]);                                \
        pT[j] = v3add(qrot(gT[p], off), pT[p]);                                \
    }                                                                          \
    anp += pd2(pD[j], pI[j]);                                                  \
    { float d = qdot(qd, qi); anr += fmaf(-d, d, 1.0f); }                      \
} while (0)

    // EE joint (leaf): dec chain skipped; loss ik-vs-tgt
#define STEP_EE(j, p) do {                                                     \
    Q qi = loadnq(ikp, ((j)-1)*8, smn, ssd, (j)*8);                            \
    Q qt = loadnq(tgp, (j)*8,     smn, ssd, (j)*8);                            \
    Q gt = qmul(qc0, qt);                                                      \
    V3 off = V3{soff[3*(j)], soff[3*(j)+1], soff[3*(j)+2]};                    \
    V3 Pi = v3add(qrot(gI[p], off), pI[p]);                                    \
    V3 Pt = v3add(qrot(gT[p], off), pT[p]);                                    \
    aep += pd2(Pi, Pt);                                                        \
    { float d = qdot(qi, gt); aer += fmaf(-d, d, 1.0f); }                      \
} while (0)

    STEP_NS(1, 0);  STEP_NS(2, 1);  STEP_NS(3, 2);   STEP_EE(4, 3);
    STEP_NS(5, 0);  STEP_NS(6, 5);  STEP_NS(7, 6);   STEP_EE(8, 7);
    STEP_NS(9, 0);  STEP_NS(10, 9); STEP_NS(11, 10);
    STEP_NS(12, 11); STEP_EE(13, 12);
    STEP_NS(14, 11); STEP_NS(15, 14); STEP_NS(16, 15); STEP_EE(17, 16);
    STEP_NS(18, 11); STEP_NS(19, 18); STEP_NS(20, 19); STEP_EE(21, 20);

#undef STEP_NS
#undef STEP_EE

    const float NBT = 65536.0f;
    float s = aep * (1.0f / (NBT * 15.0f))
            + aer * (8.0f / (NBT * 45.0f))
            + anp * (0.1f / (NBT * 48.0f))
            + anr * (0.8f / (NBT * 144.0f));

    // block reduction -> deterministic per-block partial
#pragma unroll
    for (int o = 16; o; o >>= 1) s += __shfl_down_sync(0xffffffffu, s, o);
    __shared__ float ws[NTHR / 32];
    __shared__ bool is_last;
    if ((threadIdx.x & 31) == 0) ws[threadIdx.x >> 5] = s;
    __syncthreads();
    if (threadIdx.x == 0) {
        float v = 0.0f;
#pragma unroll
        for (int i = 0; i < NTHR / 32; i++) v += ws[i];
        g_part[blockIdx.x] = v;
        __threadfence();
        unsigned int old = atomicAdd(&g_ctr, 1u);
        is_last = (old == NBLK - 1);
    }
    __syncthreads();

    // last-arriving block does the deterministic final reduction
    if (is_last && threadIdx.x < 32) {
        volatile float* vp = g_part;
        float v = 0.0f;
#pragma unroll
        for (int i = 0; i < NBLK / 32; i++) v += vp[threadIdx.x + i * 32];
#pragma unroll
        for (int o = 16; o; o >>= 1) v += __shfl_down_sync(0xffffffffu, v, o);
        if (threadIdx.x == 0) {
            out[0] = v;
            g_ctr = 0;   // reset for next graph replay
        }
    }
}

extern "C" void kernel_launch(void* const* d_in, const int* in_sizes, int n_in,
                              void* d_out, int out_size) {
    // metadata order: input(unused), input_ik, input_decoder, target, mean_dqs, std_dqs, offsets
    const float* ik   = (const float*)d_in[1];
    const float* dec  = (const float*)d_in[2];
    const float* tgt  = (const float*)d_in[3];
    const float* mean = (const float*)d_in[4];
    const float* stdv = (const float*)d_in[5];
    const float* offs = (const float*)d_in[6];
    float* out = (float*)d_out;

    fk_loss_kernel<<<NBLK, NTHR>>>(ik, dec, tgt, mean, stdv, offs, out);
}